// round 11
// baseline (speedup 1.0000x reference)
#include <cuda_runtime.h>

// CustomRouterRouter — reference-rounding-matched (Eigen/NEON gemv realization),
// full (row,e,lane) thread split + 8-stage cp.async pipeline, warp-private
// staging (no block barriers).
//
// Numerics (LOCKED, rel_err 3.06e-5): per (row,e), 4 fp32 lane accumulators,
// lane j takes k ≡ j (mod 4), fused FMA, ascending k; predux (a0+a2)+(a1+a3);
// single-rounding epilogue (+b, den add, IEEE div, mul-then-add).
//
// Thread = (row, e, j): 65536 chains, 2048 warps (~14/SM). Each 32-thread
// block owns 4 rows; the warp stages its own x tile AND its own W-slice copy
// via cp.async.cg, so __syncwarp is the only barrier. STG=8 gives ~7 stages
// of lookahead (≫ DRAM latency).

#define FT   0.5f
#define PKT  16            // float4 packets per stage per row
#define STG  8             // pipeline stages
#define RPB  4             // rows per block
#define THR  32            // 4 rows x 2 e x 4 lanes

__device__ __forceinline__ void cp_async16(void* smem_dst, const void* gmem_src) {
    unsigned saddr = (unsigned)__cvta_generic_to_shared(smem_dst);
    asm volatile("cp.async.cg.shared.global [%0], [%1], 16;\n"
                 :: "r"(saddr), "l"(gmem_src));
}
__device__ __forceinline__ void cp_commit() {
    asm volatile("cp.async.commit_group;\n" ::: "memory");
}
__device__ __forceinline__ void cp_wait() {
    asm volatile("cp.async.wait_group %0;\n" :: "n"(STG - 1) : "memory");
}

__global__ __launch_bounds__(THR) void router_lane_kernel(
    const float4* __restrict__ x4,
    const float*  __restrict__ weights,
    const float4* __restrict__ W4,
    const float*  __restrict__ b,
    float*        __restrict__ out,
    int L, int Hv)
{
    // +1 float4 pad per row -> conflict-free scalar LDS.
    __shared__ float4 sx[STG][RPB][PKT + 1];
    __shared__ float4 sw[STG][2][PKT + 1];

    const int tid     = threadIdx.x;
    const int j       = tid & 3;            // NEON lane
    const int e       = (tid >> 2) & 1;     // expert
    const int rloc    = tid >> 3;           // 0..3
    const int rowbase = blockIdx.x * RPB;
    const int row     = rowbase + rloc;

    const float4* __restrict__ xblk = x4 + (size_t)rowbase * Hv;

    const int nstages = Hv / PKT;           // 64

    // x: 2 packets per thread (own row, coalesced 128B per 8-thread group).
    // w: 1 packet per thread (warp-private copy of both W rows' slice).
    const int xp  = tid & 7;                // packet base within row
    const int we  = tid >> 4;
    const int wp  = tid & 15;

    auto issue = [&](int s) {
        const int st   = s & (STG - 1);
        const int gpkt = s * PKT;
        cp_async16(&sx[st][rloc][xp],     &xblk[(size_t)rloc * Hv + gpkt + xp]);
        cp_async16(&sx[st][rloc][xp + 8], &xblk[(size_t)rloc * Hv + gpkt + xp + 8]);
        cp_async16(&sw[st][we][wp],       &W4[(size_t)we * Hv + gpkt + wp]);
        cp_commit();
    };

    #pragma unroll
    for (int s = 0; s < STG - 1; s++) issue(s);

    // One chain per thread: acc = sum_p x[row][4p+j] * W[e][4p+j], ascending p.
    float acc = 0.f;

    #pragma unroll 1
    for (int s = 0; s < nstages; s++) {
        if (s + STG - 1 < nstages) issue(s + STG - 1);
        else                       cp_commit();

        cp_wait();
        __syncwarp();

        const int st = s & (STG - 1);
        const float* xf = reinterpret_cast<const float*>(&sx[st][rloc][0]) + j;
        const float* wf = reinterpret_cast<const float*>(&sw[st][e][0]) + j;
        #pragma unroll
        for (int p = 0; p < PKT; p++)
            acc = fmaf(xf[4 * p], wf[4 * p], acc);
        __syncwarp();
    }

    // Predux across the 4 lane threads, Eigen NEON order: (a0+a2)+(a1+a3).
    // (IEEE fp add is commutative, so every lane computes the same value.)
    float v = __shfl_xor_sync(0xffffffffu, acc, 2);
    float t = __fadd_rn(acc, v);
    v = __shfl_xor_sync(0xffffffffu, t, 1);
    const float A = __fadd_rn(t, v);

    // lin_e = A_e + b_e (single rounding); den via e-partner (lane xor 4).
    const float lin   = __fadd_rn(A, __ldg(&b[e]));
    const float other = __shfl_xor_sync(0xffffffffu, lin, 4);
    const float den   = __fadd_rn((e == 0) ? lin : other,
                                  (e == 0) ? other : lin);
    const float l     = __fdiv_rn(lin, den);

    // hs = weights[row // (L/2)][0]; weights is (2,2) row-major.
    const float hs = __ldg(&weights[(row >= (L >> 1)) ? 2 : 0]);

    float rr_self, rr2;
    if (hs >= FT) {
        rr2     = __fdiv_rn(__fsub_rn(1.0f, hs), 1.0f - FT);
        rr_self = (e == 0) ? __fdiv_rn(__fsub_rn(hs, FT), 1.0f - FT) : 0.0f;
    } else {
        rr2     = __fdiv_rn(hs, FT);
        rr_self = (e == 0) ? 0.0f : __fdiv_rn(__fsub_rn(FT, hs), FT);
    }

    if (j == 0)
        out[row * 2 + e] = __fadd_rn(rr_self, __fmul_rn(rr2, l));
}

extern "C" void kernel_launch(void* const* d_in, const int* in_sizes, int n_in,
                              void* d_out, int out_size) {
    const float* x       = (const float*)d_in[0];
    const float* weights = (const float*)d_in[1];
    const float* W       = (const float*)d_in[2];
    const float* b       = (const float*)d_in[3];
    float* out = (float*)d_out;

    const int E  = in_sizes[3];            // 2
    const int H  = in_sizes[2] / E;        // 4096
    const int L  = in_sizes[0] / H;        // 8192
    const int Hv = H / 4;                  // 1024

    const int blocks = L / RPB;            // 2048

    router_lane_kernel<<<blocks, THR>>>((const float4*)x, weights,
                                        (const float4*)W, b, out, L, Hv);
}

// round 12
// speedup vs baseline: 1.2971x; 1.2971x over previous
#include <cuda_runtime.h>

// CustomRouterRouter — reference-rounding-matched (Eigen/NEON gemv realization),
// lane-split threads + cp.async pipeline + pre-interleaved W (halves w-LDS ops).
//
// Numerics (LOCKED, rel_err 3.06e-5): per (row,e), 4 fp32 lane accumulators,
// lane j takes k ≡ j (mod 4), fused FMA, ascending k; predux (a0+a2)+(a1+a3);
// single-rounding epilogue (+b, den add, IEEE div, mul-then-add).
//
// Perf model (validated R9-R11): kernel is LSU-op bound:
//   dur ∝ LDS warp-ops + 8*LDGSTS warp-ops.
// Thread = (row, j), both e's in-thread (x scalar feeds 2 FMAs). W is
// pre-interleaved (w0[k], w1[k]) by a tiny prep kernel into __device__
// scratch, so the consumer does 1 x-LDS.32 + 1 w-LDS.64 per packet
// (was 1 + 2 scalar). 1024 warps, 6-stage pipeline, warp-private staging.

#define FT   0.5f
#define PKT  16            // float4 packets per stage per row
#define STG  6             // pipeline stages
#define RPB  8             // rows per block
#define THR  32            // one warp: 8 rows x 4 lanes

__device__ float2 g_wint[4096];   // (W[0][k], W[1][k]) pairs, 32 KB scratch

__global__ void interleave_w_kernel(const float* __restrict__ W, int H) {
    int k = blockIdx.x * blockDim.x + threadIdx.x;
    if (k < H) g_wint[k] = make_float2(W[k], W[H + k]);
}

__device__ __forceinline__ void cp_async16(void* smem_dst, const void* gmem_src) {
    unsigned saddr = (unsigned)__cvta_generic_to_shared(smem_dst);
    asm volatile("cp.async.cg.shared.global [%0], [%1], 16;\n"
                 :: "r"(saddr), "l"(gmem_src));
}
__device__ __forceinline__ void cp_commit() {
    asm volatile("cp.async.commit_group;\n" ::: "memory");
}
__device__ __forceinline__ void cp_wait() {
    asm volatile("cp.async.wait_group %0;\n" :: "n"(STG - 1) : "memory");
}

__global__ __launch_bounds__(THR) void router_lane_kernel(
    const float4* __restrict__ x4,
    const float*  __restrict__ weights,
    const float*  __restrict__ b,
    float*        __restrict__ out,
    int L, int Hv)
{
    // x: [stage][row][packet], +1 float4 row pad -> conflict-free scalar LDS.
    // w: [stage][33 float4] = 32 float4 of interleaved (w0,w1) pairs + pad.
    __shared__ float4 sx[STG][RPB][PKT + 1];
    __shared__ float4 sw[STG][33];

    const int tid     = threadIdx.x;
    const int rloc    = tid >> 2;          // 0..7
    const int j       = tid & 3;           // NEON lane
    const int rowbase = blockIdx.x * RPB;
    const int row     = rowbase + rloc;

    const float4* __restrict__ xblk = x4 + (size_t)rowbase * Hv;
    const float4* __restrict__ wi4  = (const float4*)g_wint;

    const int nstages = Hv / PKT;          // 64

    auto issue = [&](int s) {
        const int st   = s & 7;            // STG=6 < 8; use mod via table below
        const int stm  = st >= STG ? st - STG : st;   // s % STG (s increments by 1)
        const int gpkt = s * PKT;
        // x: 8 rows x 16 packets = 128 float4, 4 per thread, coalesced.
        #pragma unroll
        for (int k = 0; k < (RPB * PKT) / THR; k++) {
            const int idx = tid + k * THR;
            const int r   = idx >> 4;
            const int p   = idx & 15;
            cp_async16(&sx[stm][r][p], &xblk[(size_t)r * Hv + gpkt + p]);
        }
        // w interleaved slice: 32 float4 per stage (64 k-values x 2 e).
        cp_async16(&sw[stm][tid], &wi4[(size_t)s * 32 + tid]);
        cp_commit();
    };

    // NOTE: replace the st/stm hack with a proper running index:
    // (kept simple: compute s % STG directly)
    #pragma unroll
    for (int s = 0; s < STG - 1; s++) {
        const int stm  = s % STG;
        const int gpkt = s * PKT;
        #pragma unroll
        for (int k = 0; k < (RPB * PKT) / THR; k++) {
            const int idx = tid + k * THR;
            const int r   = idx >> 4;
            const int p   = idx & 15;
            cp_async16(&sx[stm][r][p], &xblk[(size_t)r * Hv + gpkt + p]);
        }
        cp_async16(&sw[stm][tid], &wi4[(size_t)s * 32 + tid]);
        cp_commit();
    }

    // Two chains per thread (e=0,1), lane j, ascending global packet order.
    float acc0 = 0.f, acc1 = 0.f;

    int stc = 0;                            // s % STG for consume
    int stp = (STG - 1) % STG;              // (s + STG-1) % STG for produce

    #pragma unroll 1
    for (int s = 0; s < nstages; s++) {
        if (s + STG - 1 < nstages) {
            const int gpkt = (s + STG - 1) * PKT;
            #pragma unroll
            for (int k = 0; k < (RPB * PKT) / THR; k++) {
                const int idx = tid + k * THR;
                const int r   = idx >> 4;
                const int p   = idx & 15;
                cp_async16(&sx[stp][r][p], &xblk[(size_t)r * Hv + gpkt + p]);
            }
            cp_async16(&sw[stp][tid], &wi4[(size_t)(s + STG - 1) * 32 + tid]);
        }
        cp_commit();

        cp_wait();
        __syncwarp();

        const float*  xf = reinterpret_cast<const float*>(&sx[stc][rloc][0]) + j;
        const float2* wf = reinterpret_cast<const float2*>(&sw[stc][0]) + j;
        #pragma unroll
        for (int p = 0; p < PKT; p++) {
            const float  xs = xf[4 * p];
            const float2 wp = wf[4 * p];
            acc0 = fmaf(xs, wp.x, acc0);
            acc1 = fmaf(xs, wp.y, acc1);
        }
        __syncwarp();

        stc = (stc + 1 == STG) ? 0 : stc + 1;
        stp = (stp + 1 == STG) ? 0 : stp + 1;
    }

    // Predux across the 4 lane threads, Eigen NEON order: (a0+a2)+(a1+a3).
    float v;
    v = __shfl_xor_sync(0xffffffffu, acc0, 2);
    float t0 = __fadd_rn(acc0, v);
    v = __shfl_xor_sync(0xffffffffu, t0, 1);
    const float A0 = __fadd_rn(t0, v);

    v = __shfl_xor_sync(0xffffffffu, acc1, 2);
    float t1 = __fadd_rn(acc1, v);
    v = __shfl_xor_sync(0xffffffffu, t1, 1);
    const float A1 = __fadd_rn(t1, v);

    // Single-rounding epilogue (all threads compute; lane j==0 writes).
    const float lin0 = __fadd_rn(A0, __ldg(&b[0]));
    const float lin1 = __fadd_rn(A1, __ldg(&b[1]));
    const float den  = __fadd_rn(lin0, lin1);
    const float l0   = __fdiv_rn(lin0, den);
    const float l1   = __fdiv_rn(lin1, den);

    const float hs = __ldg(&weights[(row >= (L >> 1)) ? 2 : 0]);
    float rr0, rr1, rr2;
    if (hs >= FT) {
        rr2 = __fdiv_rn(__fsub_rn(1.0f, hs), 1.0f - FT);
        rr0 = __fdiv_rn(__fsub_rn(hs, FT), 1.0f - FT);
        rr1 = 0.0f;
    } else {
        rr2 = __fdiv_rn(hs, FT);
        rr0 = 0.0f;
        rr1 = __fdiv_rn(__fsub_rn(FT, hs), FT);
    }

    if (j == 0) {
        out[row * 2 + 0] = __fadd_rn(rr0, __fmul_rn(rr2, l0));
        out[row * 2 + 1] = __fadd_rn(rr1, __fmul_rn(rr2, l1));
    }
}

extern "C" void kernel_launch(void* const* d_in, const int* in_sizes, int n_in,
                              void* d_out, int out_size) {
    const float* x       = (const float*)d_in[0];
    const float* weights = (const float*)d_in[1];
    const float* W       = (const float*)d_in[2];
    const float* b       = (const float*)d_in[3];
    float* out = (float*)d_out;

    const int E  = in_sizes[3];            // 2
    const int H  = in_sizes[2] / E;        // 4096
    const int L  = in_sizes[0] / H;        // 8192
    const int Hv = H / 4;                  // 1024

    interleave_w_kernel<<<(H + 255) / 256, 256>>>(W, H);

    const int blocks = L / RPB;            // 1024
    router_lane_kernel<<<blocks, THR>>>((const float4*)x, weights, b,
                                        out, L, Hv);
}

// round 13
// speedup vs baseline: 1.5523x; 1.1967x over previous
#include <cuda_runtime.h>

// CustomRouterRouter — reference-rounding-matched (Eigen/NEON gemv realization).
// Persistent interleaved W in smem + warp-private cp.async x pipeline.
//
// Numerics (LOCKED, rel_err 3.06e-5): per (row,e), 4 fp32 lane accumulators,
// lane j takes k ≡ j (mod 4), fused FMA, ascending k; predux (a0+a2)+(a1+a3);
// single-rounding epilogue (+b, den add, IEEE div, mul-then-add).
//
// Perf model (validated R9-R12): LSU-op bound. Cuts vs R12:
//  - W interleaved once per block into persistent smem (no prep kernel,
//    no per-stage w LDGSTS/writes); consumer reads broadcast LDS.64.
//  - 2-warp blocks (16 rows): 512 blocks, 45.8 KB smem -> 4 blocks/SM,
//    8 warps/SM, single wave. Steady-state sync = __syncwarp only.

#define FT   0.5f
#define PKT  16            // float4 packets per stage per row
#define STG  3             // pipeline stages (wait_group 2)
#define RPB  16            // rows per block (8 per warp)
#define THR  64            // 2 warps

__device__ __forceinline__ void cp_async16(void* smem_dst, const void* gmem_src) {
    unsigned saddr = (unsigned)__cvta_generic_to_shared(smem_dst);
    asm volatile("cp.async.cg.shared.global [%0], [%1], 16;\n"
                 :: "r"(saddr), "l"(gmem_src));
}
__device__ __forceinline__ void cp_commit() {
    asm volatile("cp.async.commit_group;\n" ::: "memory");
}
__device__ __forceinline__ void cp_wait() {
    asm volatile("cp.async.wait_group %0;\n" :: "n"(STG - 1) : "memory");
}

__global__ __launch_bounds__(THR) void router_lane_kernel(
    const float4* __restrict__ x4,
    const float*  __restrict__ weights,
    const float*  __restrict__ W,
    const float*  __restrict__ b,
    float*        __restrict__ out,
    int L, int Hv)
{
    // x: [stage][row][packet], +1 float4 row pad (stride 68 words ≡ 4 mod 32
    // -> conflict-free scalar LDS across the warp).
    // swp: persistent interleaved (W0[k], W1[k]) pairs, 32 KB.
    __shared__ float4 sx[STG][RPB][PKT + 1];   // 13.1 KB
    __shared__ float2 swp[4096];               // 32 KB  (total 45.8 KB static)

    const int tid     = threadIdx.x;
    const int lane    = tid & 31;
    const int wid     = tid >> 5;          // warp in block
    const int rloc    = tid >> 2;          // 0..15 (block-local row)
    const int j       = tid & 3;           // NEON lane
    const int rowbase = blockIdx.x * RPB;
    const int row     = rowbase + rloc;
    const int H       = Hv * 4;

    // ── Prologue: interleave W into persistent smem (once per block). ──
    for (int k0 = tid * 4; k0 < H; k0 += THR * 4) {
        const float4 w0 = *reinterpret_cast<const float4*>(W + k0);
        const float4 w1 = *reinterpret_cast<const float4*>(W + H + k0);
        swp[k0 + 0] = make_float2(w0.x, w1.x);
        swp[k0 + 1] = make_float2(w0.y, w1.y);
        swp[k0 + 2] = make_float2(w0.z, w1.z);
        swp[k0 + 3] = make_float2(w0.w, w1.w);
    }
    __syncthreads();

    // ── Warp-private x staging: each warp owns rows [wid*8, wid*8+8). ──
    const float4* __restrict__ xwarp = x4 + (size_t)(rowbase + wid * 8) * Hv;

    auto issue = [&](int s, int st) {
        const int gp = s * PKT;
        #pragma unroll
        for (int k = 0; k < 4; k++) {
            const int idx = lane + k * 32;   // 0..127
            const int r   = idx >> 4;        // 0..7
            const int p   = idx & 15;
            cp_async16(&sx[st][wid * 8 + r][p], &xwarp[(size_t)r * Hv + gp + p]);
        }
        cp_commit();
    };

    issue(0, 0);
    issue(1, 1);

    // Two chains per thread (e=0,1), lane j, ascending global packet order.
    float acc0 = 0.f, acc1 = 0.f;

    const int nstages = Hv / PKT;          // 64
    int stc = 0;                            // consume slot
    int stp = STG - 1;                      // produce slot

    #pragma unroll 1
    for (int s = 0; s < nstages; s++) {
        if (s + STG - 1 < nstages) issue(s + STG - 1, stp);
        else                       cp_commit();

        cp_wait();
        __syncwarp();

        const float*  xf = reinterpret_cast<const float*>(&sx[stc][rloc][0]) + j;
        const float2* wf = swp + s * (PKT * 4) + j;
        #pragma unroll
        for (int p = 0; p < PKT; p++) {
            const float  xs = xf[4 * p];
            const float2 wv = wf[4 * p];
            acc0 = fmaf(xs, wv.x, acc0);
            acc1 = fmaf(xs, wv.y, acc1);
        }
        __syncwarp();

        stc = (stc + 1 == STG) ? 0 : stc + 1;
        stp = (stp + 1 == STG) ? 0 : stp + 1;
    }

    // Predux across the 4 lane threads, Eigen NEON order: (a0+a2)+(a1+a3).
    float v;
    v = __shfl_xor_sync(0xffffffffu, acc0, 2);
    float t0 = __fadd_rn(acc0, v);
    v = __shfl_xor_sync(0xffffffffu, t0, 1);
    const float A0 = __fadd_rn(t0, v);

    v = __shfl_xor_sync(0xffffffffu, acc1, 2);
    float t1 = __fadd_rn(acc1, v);
    v = __shfl_xor_sync(0xffffffffu, t1, 1);
    const float A1 = __fadd_rn(t1, v);

    // Single-rounding epilogue (all threads compute; lane j==0 writes).
    const float lin0 = __fadd_rn(A0, __ldg(&b[0]));
    const float lin1 = __fadd_rn(A1, __ldg(&b[1]));
    const float den  = __fadd_rn(lin0, lin1);
    const float l0   = __fdiv_rn(lin0, den);
    const float l1   = __fdiv_rn(lin1, den);

    const float hs = __ldg(&weights[(row >= (L >> 1)) ? 2 : 0]);
    float rr0, rr1, rr2;
    if (hs >= FT) {
        rr2 = __fdiv_rn(__fsub_rn(1.0f, hs), 1.0f - FT);
        rr0 = __fdiv_rn(__fsub_rn(hs, FT), 1.0f - FT);
        rr1 = 0.0f;
    } else {
        rr2 = __fdiv_rn(hs, FT);
        rr0 = 0.0f;
        rr1 = __fdiv_rn(__fsub_rn(FT, hs), FT);
    }

    if (j == 0) {
        out[row * 2 + 0] = __fadd_rn(rr0, __fmul_rn(rr2, l0));
        out[row * 2 + 1] = __fadd_rn(rr1, __fmul_rn(rr2, l1));
    }
}

extern "C" void kernel_launch(void* const* d_in, const int* in_sizes, int n_in,
                              void* d_out, int out_size) {
    const float* x       = (const float*)d_in[0];
    const float* weights = (const float*)d_in[1];
    const float* W       = (const float*)d_in[2];
    const float* b       = (const float*)d_in[3];
    float* out = (float*)d_out;

    const int E  = in_sizes[3];            // 2
    const int H  = in_sizes[2] / E;        // 4096
    const int L  = in_sizes[0] / H;        // 8192
    const int Hv = H / 4;                  // 1024

    const int blocks = L / RPB;            // 512

    router_lane_kernel<<<blocks, THR>>>((const float4*)x, weights, W, b,
                                        out, L, Hv);
}

// round 14
// speedup vs baseline: 1.6612x; 1.0702x over previous
#include <cuda_runtime.h>

// CustomRouterRouter — reference-rounding-matched (Eigen/NEON gemv realization).
// Packed f32x2 FMA (FFMA2) over j-pairs + persistent W smem + cp.async pipeline.
//
// Numerics (LOCKED, rel_err 3.06e-5): per (row,e), 4 fp32 lane accumulators,
// lane j takes k ≡ j (mod 4), fused FMA, ascending k; predux (a0+a2)+(a1+a3);
// single-rounding epilogue (+b, den add, IEEE div, mul-then-add).
// f32x2 lanes are independent IEEE fp32 ops -> bit-identical to scalar fmaf;
// add.rn.f32x2 predux = (__fadd_rn(a0,a2), __fadd_rn(a1,a3)) exactly.
//
// Perf model (validated R9-R13): SMSP issue-bound at ~129 cyc/warp-stage.
// Thread = (row, e, jpair): per packet 1 x-LDS.64 + 1 w-LDS.64 + 1 FFMA2
// (3 issues, was 4). Per warp-stage issues 74 -> ~58.

#define FT   0.5f
#define PKT  16            // float4 packets per stage per row
#define STG  4             // pipeline stages (wait_group 3)
#define RPB  16            // rows per block (8 per warp)
#define THR  64            // 2 warps
#define WPAD 4100          // W row stride in floats (4096 + 4: bank shift + 16B align)

typedef unsigned long long u64;

__device__ __forceinline__ void cp_async16(void* smem_dst, const void* gmem_src) {
    unsigned saddr = (unsigned)__cvta_generic_to_shared(smem_dst);
    asm volatile("cp.async.cg.shared.global [%0], [%1], 16;\n"
                 :: "r"(saddr), "l"(gmem_src));
}
__device__ __forceinline__ void cp_commit() {
    asm volatile("cp.async.commit_group;\n" ::: "memory");
}
__device__ __forceinline__ void cp_wait() {
    asm volatile("cp.async.wait_group %0;\n" :: "n"(STG - 1) : "memory");
}
__device__ __forceinline__ void ffma2(u64& acc, u64 x, u64 w) {
    asm("fma.rn.f32x2 %0, %1, %2, %3;" : "=l"(acc) : "l"(x), "l"(w), "l"(acc));
}

__global__ __launch_bounds__(THR) void router_lane_kernel(
    const float4* __restrict__ x4,
    const float*  __restrict__ weights,
    const float*  __restrict__ W,
    const float*  __restrict__ b,
    float*        __restrict__ out,
    int L, int Hv)
{
    // x: [stage][row][packet], +1 float4 row pad (stride 68 words ≡ 4 mod 32).
    // sw: plain W rows, stride 4100 words (bank shift 4 between e0/e1).
    __shared__ float4 sx[STG][RPB][PKT + 1];   // 17.4 KB
    __shared__ float  sw[2 * WPAD];            // 32.8 KB

    const int tid     = threadIdx.x;
    const int lane    = tid & 31;
    const int wid     = tid >> 5;          // warp in block
    const int jp      = tid & 1;           // j-pair: j = 2*jp, 2*jp+1
    const int e       = (tid >> 1) & 1;    // expert
    const int rloc    = tid >> 2;          // 0..15 (block-local row)
    const int rowbase = blockIdx.x * RPB;
    const int row     = rowbase + rloc;
    const int H       = Hv * 4;

    // ── Prologue: copy W into smem (plain layout, padded rows). ──
    for (int k = tid * 4; k < H; k += THR * 4) {
        *reinterpret_cast<float4*>(&sw[k])        = *reinterpret_cast<const float4*>(W + k);
        *reinterpret_cast<float4*>(&sw[WPAD + k]) = *reinterpret_cast<const float4*>(W + H + k);
    }
    __syncthreads();

    // ── Warp-private x staging: each warp owns rows [wid*8, wid*8+8). ──
    const float4* __restrict__ xwarp = x4 + (size_t)(rowbase + wid * 8) * Hv;

    auto issue = [&](int s, int st) {
        const int gp = s * PKT;
        #pragma unroll
        for (int k = 0; k < 4; k++) {
            const int idx = lane + k * 32;   // 0..127
            const int r   = idx >> 4;        // 0..7
            const int p   = idx & 15;
            cp_async16(&sx[st][wid * 8 + r][p], &xwarp[(size_t)r * Hv + gp + p]);
        }
        cp_commit();
    };

    issue(0, 0);
    issue(1, 1);
    issue(2, 2);

    // One f32x2 chain per thread: lanes (j=2jp, j=2jp+1) for expert e.
    u64 acc = 0ull;

    const int nstages = Hv / PKT;          // 64
    int stc = 0;                            // consume slot
    int stp = STG - 1;                      // produce slot

    #pragma unroll 1
    for (int s = 0; s < nstages; s++) {
        if (s + STG - 1 < nstages) issue(s + STG - 1, stp);
        else                       cp_commit();

        cp_wait();
        __syncwarp();

        // x: word offset 4p + 2jp within the row -> u64 index 2p + jp.
        const u64* xq = reinterpret_cast<const u64*>(&sx[stc][rloc][0]) + jp;
        // w: word offset e*WPAD + s*64 + 4p + 2jp -> u64 index from padded base.
        const u64* wq = reinterpret_cast<const u64*>(&sw[e * WPAD + s * (PKT * 4)]) + jp;
        #pragma unroll
        for (int p = 0; p < PKT; p++)
            ffma2(acc, xq[2 * p], wq[2 * p]);
        __syncwarp();

        stc = (stc + 1 == STG) ? 0 : stc + 1;
        stp = (stp + 1 == STG) ? 0 : stp + 1;
    }

    // Predux, Eigen NEON order. jp=0 holds (a0,a1), jp=1 holds (a2,a3).
    // add.rn.f32x2 -> (a0+a2, a1+a3), then scalar add.
    const u64 vv = __shfl_xor_sync(0xffffffffu, acc, 1);
    u64 sum2;
    asm("add.rn.f32x2 %0, %1, %2;" : "=l"(sum2) : "l"(acc), "l"(vv));
    const float slo = __uint_as_float((unsigned)(sum2 & 0xffffffffull));
    const float shi = __uint_as_float((unsigned)(sum2 >> 32));
    const float A   = __fadd_rn(slo, shi);

    // lin_e = A_e + b_e (single rounding); den via e-partner (lane xor 2).
    const float lin   = __fadd_rn(A, __ldg(&b[e]));
    const float other = __shfl_xor_sync(0xffffffffu, lin, 2);
    const float den   = __fadd_rn((e == 0) ? lin : other,
                                  (e == 0) ? other : lin);
    const float l     = __fdiv_rn(lin, den);

    // hs = weights[row // (L/2)][0]; weights is (2,2) row-major.
    const float hs = __ldg(&weights[(row >= (L >> 1)) ? 2 : 0]);

    float rr_self, rr2;
    if (hs >= FT) {
        rr2     = __fdiv_rn(__fsub_rn(1.0f, hs), 1.0f - FT);
        rr_self = (e == 0) ? __fdiv_rn(__fsub_rn(hs, FT), 1.0f - FT) : 0.0f;
    } else {
        rr2     = __fdiv_rn(hs, FT);
        rr_self = (e == 0) ? 0.0f : __fdiv_rn(__fsub_rn(FT, hs), FT);
    }

    if (jp == 0)
        out[row * 2 + e] = __fadd_rn(rr_self, __fmul_rn(rr2, l));
}

extern "C" void kernel_launch(void* const* d_in, const int* in_sizes, int n_in,
                              void* d_out, int out_size) {
    const float* x       = (const float*)d_in[0];
    const float* weights = (const float*)d_in[1];
    const float* W       = (const float*)d_in[2];
    const float* b       = (const float*)d_in[3];
    float* out = (float*)d_out;

    const int E  = in_sizes[3];            // 2
    const int H  = in_sizes[2] / E;        // 4096
    const int L  = in_sizes[0] / H;        // 8192
    const int Hv = H / 4;                  // 1024

    const int blocks = L / RPB;            // 512

    router_lane_kernel<<<blocks, THR>>>((const float4*)x, weights, W, b,
                                        out, L, Hv);
}